// round 1
// baseline (speedup 1.0000x reference)
#include <cuda_runtime.h>
#include <cstdint>

#define Hh 128
#define Ww 256
#define HW (Hh*Ww)
#define NB 4
#define CIN 256
#define Tc 64
#define CCLS 19

// ---------------- scratch (allocation-free: __device__ globals) ----------------
__device__ float g_y[NB * 128 * HW];    // concat(t1,t2): (4,128,128,256)  ~67MB
__device__ float g_x[NB * Tc * HW];     // after BN+ReLU: (4,64,128,256)   ~33MB
__device__ float g_flow[NB * 2 * HW];   // flow: (4,2,128,256)             ~1MB

// ============================================================================
// Kernel 1: both 1x1 convs (GEMM  C[64,32768] = W[64,256] * X[256,32768])
// block: 64 out-ch x 128 px, 256 threads, microtile 8ch x 4px
// ============================================================================
__global__ void __launch_bounds__(256) k_conv1x1(
    const float* __restrict__ x1, const float* __restrict__ x2,
    const float* __restrict__ w1, const float* __restrict__ w2)
{
    __shared__ float Ws[32][64];    // [k][t]
    __shared__ float Xs[32][128];   // [k][p]

    const int pt = blockIdx.x;          // 0..255 pixel tile
    const int n  = blockIdx.y;          // batch
    const int wh = blockIdx.z;          // 0: t1 path, 1: t2 path

    const float* X  = (wh ? x2 : x1) + (size_t)n * CIN * HW + pt * 128;
    const float* Wg = wh ? w2 : w1;
    float* Y = g_y + (size_t)(n * 128 + wh * 64) * HW + pt * 128;

    const int tid = threadIdx.x;
    const int cb = (tid >> 5) * 8;      // channel base (same for whole warp)
    const int pb = (tid & 31) * 4;      // pixel base

    float acc[8][4];
#pragma unroll
    for (int i = 0; i < 8; i++)
#pragma unroll
        for (int j = 0; j < 4; j++) acc[i][j] = 0.f;

    for (int k0 = 0; k0 < 256; k0 += 32) {
        for (int i = tid; i < 2048; i += 256) {
            int t = i & 63, k = i >> 6;
            Ws[k][t] = Wg[t * CIN + k0 + k];
        }
        for (int i = tid; i < 4096; i += 256) {
            int k = i >> 7, p = i & 127;
            Xs[k][p] = X[(size_t)(k0 + k) * HW + p];
        }
        __syncthreads();
#pragma unroll
        for (int k = 0; k < 32; k++) {
            float4 wa = *(const float4*)&Ws[k][cb];
            float4 wb = *(const float4*)&Ws[k][cb + 4];
            float4 xv = *(const float4*)&Xs[k][pb];
            float wv[8] = {wa.x, wa.y, wa.z, wa.w, wb.x, wb.y, wb.z, wb.w};
            float xr[4] = {xv.x, xv.y, xv.z, xv.w};
#pragma unroll
            for (int i = 0; i < 8; i++)
#pragma unroll
                for (int j = 0; j < 4; j++) acc[i][j] += wv[i] * xr[j];
        }
        __syncthreads();
    }
#pragma unroll
    for (int i = 0; i < 8; i++) {
        float4 v = make_float4(acc[i][0], acc[i][1], acc[i][2], acc[i][3]);
        *(float4*)&Y[(size_t)(cb + i) * HW + pb] = v;
    }
}

// ============================================================================
// Kernel 2: conv3x3 (128 -> 64, pad 1) + BN + ReLU
// block tile: 64 out-ch x (16x16 px), 256 threads, microtile 8ch x 8px
// Cchunk = 8 input channels per SMEM stage
// ============================================================================
__global__ void __launch_bounds__(256, 2) k_conv3x3_bn(
    const float* __restrict__ wf,
    const float* __restrict__ gamma, const float* __restrict__ beta,
    const float* __restrict__ mean,  const float* __restrict__ var)
{
    __shared__ float Xs[8 * 18 * 20];   // [cc][row(18)][col pad 20]
    __shared__ float Ws[8 * 9 * 64];    // [cc][tap][t]

    const int bx = blockIdx.x;          // 0..15 (W/16)
    const int by = blockIdx.y;          // 0..7  (H/16)
    const int n  = blockIdx.z;

    const int tid = threadIdx.x;
    const int cb  = (tid >> 5) * 8;     // channel octet (warp-uniform)
    const int g   = tid & 31;
    const int r   = g >> 1;             // 0..15 output row in tile
    const int hx  = (g & 1) * 8;        // 0 or 8: output col base

    float acc[8][8];
#pragma unroll
    for (int i = 0; i < 8; i++)
#pragma unroll
        for (int j = 0; j < 8; j++) acc[i][j] = 0.f;

    const float* Yb = g_y + (size_t)n * 128 * HW;

    for (int ch0 = 0; ch0 < 128; ch0 += 8) {
        // stage input halo tile 8 x 18 x 18 (pad cols 18,19 untouched, never used)
        for (int i = tid; i < 8 * 18 * 18; i += 256) {
            int cc = i / 324;
            int rem = i - cc * 324;
            int ry = rem / 18, rx = rem - (rem / 18) * 18;
            int gy = by * 16 + ry - 1;
            int gx = bx * 16 + rx - 1;
            float v = 0.f;
            if ((unsigned)gy < (unsigned)Hh && (unsigned)gx < (unsigned)Ww)
                v = Yb[(size_t)(ch0 + cc) * HW + gy * Ww + gx];
            Xs[cc * 360 + ry * 20 + rx] = v;
        }
        // stage weights as [cc][tap][t] so the t-dim is float4-loadable
        for (int i = tid; i < 8 * 9 * 64; i += 256) {
            int t = i & 63;
            int tap = (i >> 6) % 9;
            int cc = i / 576;
            Ws[cc * 576 + tap * 64 + t] = wf[t * (128 * 9) + (ch0 + cc) * 9 + tap];
        }
        __syncthreads();

#pragma unroll
        for (int cc = 0; cc < 8; cc++) {
#pragma unroll
            for (int dy = 0; dy < 3; dy++) {
                const float* xp = &Xs[cc * 360 + (r + dy) * 20 + hx];
                float xr[12];
                *(float4*)&xr[0] = *(const float4*)&xp[0];
                *(float4*)&xr[4] = *(const float4*)&xp[4];
                *(float4*)&xr[8] = *(const float4*)&xp[8];
#pragma unroll
                for (int dx = 0; dx < 3; dx++) {
                    const float* wp = &Ws[cc * 576 + (dy * 3 + dx) * 64 + cb];
                    float4 wa = *(const float4*)&wp[0];
                    float4 wb = *(const float4*)&wp[4];
                    float wv[8] = {wa.x, wa.y, wa.z, wa.w, wb.x, wb.y, wb.z, wb.w};
#pragma unroll
                    for (int i = 0; i < 8; i++)
#pragma unroll
                        for (int j = 0; j < 8; j++)
                            acc[i][j] += wv[i] * xr[dx + j];
                }
            }
        }
        __syncthreads();
    }

    // epilogue: BN + ReLU, store to g_x
    const int oy = by * 16 + r;
    const int ox = bx * 16 + hx;
#pragma unroll
    for (int i = 0; i < 8; i++) {
        int t = cb + i;
        float s = gamma[t] * rsqrtf(var[t] + 1e-5f);
        float b = beta[t] - mean[t] * s;
        float o[8];
#pragma unroll
        for (int j = 0; j < 8; j++) {
            float v = acc[i][j] * s + b;
            o[j] = v > 0.f ? v : 0.f;
        }
        float* dst = g_x + (size_t)((n * Tc + t) * Hh + oy) * Ww + ox;
        *(float4*)&dst[0] = make_float4(o[0], o[1], o[2], o[3]);
        *(float4*)&dst[4] = make_float4(o[4], o[5], o[6], o[7]);
    }
}

// ============================================================================
// Kernel 3: conv3x3 (64 -> 2, pad 1) -> flow
// block: 8x32 px tile, 1 px/thread, both output channels
// ============================================================================
__global__ void __launch_bounds__(256) k_flowconv(const float* __restrict__ w2)
{
    __shared__ float Xs[8 * 10 * 36];   // [cc][row(10)][col(34) pad 36]
    __shared__ float Ws[2 * 64 * 9];

    const int bx = blockIdx.x;          // 0..7  (W/32)
    const int by = blockIdx.y;          // 0..15 (H/8)
    const int n  = blockIdx.z;

    const int tid = threadIdx.x;
    const int py = tid >> 5;            // 0..7
    const int px = tid & 31;            // 0..31

    for (int i = tid; i < 1152; i += 256) Ws[i] = w2[i];

    float a0 = 0.f, a1 = 0.f;
    const float* Xb = g_x + (size_t)n * Tc * HW;

    for (int c0 = 0; c0 < 64; c0 += 8) {
        for (int i = tid; i < 8 * 10 * 34; i += 256) {
            int cc = i / 340;
            int rem = i - cc * 340;
            int ry = rem / 34, rx = rem - (rem / 34) * 34;
            int gy = by * 8 + ry - 1;
            int gx = bx * 32 + rx - 1;
            float v = 0.f;
            if ((unsigned)gy < (unsigned)Hh && (unsigned)gx < (unsigned)Ww)
                v = Xb[(size_t)(c0 + cc) * HW + gy * Ww + gx];
            Xs[cc * 360 + ry * 36 + rx] = v;
        }
        __syncthreads();
#pragma unroll
        for (int cc = 0; cc < 8; cc++) {
            int c = c0 + cc;
#pragma unroll
            for (int dy = 0; dy < 3; dy++) {
#pragma unroll
                for (int dx = 0; dx < 3; dx++) {
                    float xv = Xs[cc * 360 + (py + dy) * 36 + (px + dx)];
                    int tap = dy * 3 + dx;
                    a0 += Ws[c * 9 + tap] * xv;
                    a1 += Ws[(64 + c) * 9 + tap] * xv;
                }
            }
        }
        __syncthreads();
    }

    const int oy = by * 8 + py, ox = bx * 32 + px;
    g_flow[((size_t)(n * 2 + 0) * Hh + oy) * Ww + ox] = a0;
    g_flow[((size_t)(n * 2 + 1) * Hh + oy) * Ww + ox] = a1;
}

// ============================================================================
// Kernel 4: flow_warp with torch repeat(c,1,1,1) batch-aliasing:
//   image (n,ch) uses flow batch (n*19+ch) % 4
// align_corners=False, bilinear, zero padding.
// ============================================================================
__global__ void __launch_bounds__(256) k_warp(
    const float* __restrict__ pred, float* __restrict__ out)
{
    const int idx = blockIdx.x * 256 + threadIdx.x;   // exactly 4*19*128*256 threads
    const int x = idx & (Ww - 1);
    const int y = (idx >> 8) & (Hh - 1);
    const int t = idx >> 15;                          // n*19+ch, 0..75
    const int fb = t & 3;                             // (n*19+ch)%4

    const float fx = g_flow[((size_t)(fb * 2 + 0) * Hh + y) * Ww + x];
    const float fy = g_flow[((size_t)(fb * 2 + 1) * Hh + y) * Ww + x];

    const float gx = -1.f + 2.f * (float)x / (float)(Ww - 1);
    const float gy = -1.f + 2.f * (float)y / (float)(Hh - 1);
    const float sx = gx + fx / (float)Ww;
    const float sy = gy + fy / (float)Hh;
    const float ix = ((sx + 1.f) * (float)Ww - 1.f) * 0.5f;
    const float iy = ((sy + 1.f) * (float)Hh - 1.f) * 0.5f;

    const float x0f = floorf(ix), y0f = floorf(iy);
    const float wx = ix - x0f, wy = iy - y0f;
    const int x0 = (int)x0f, y0 = (int)y0f;

    const float* img = pred + (size_t)t * HW;
    auto samp = [&](int yy, int xx) -> float {
        return (xx >= 0 && xx < Ww && yy >= 0 && yy < Hh) ? img[yy * Ww + xx] : 0.f;
    };
    const float v00 = samp(y0, x0);
    const float v01 = samp(y0, x0 + 1);
    const float v10 = samp(y0 + 1, x0);
    const float v11 = samp(y0 + 1, x0 + 1);

    const float top = v00 * (1.f - wx) + v01 * wx;
    const float bot = v10 * (1.f - wx) + v11 * wx;
    out[idx] = top * (1.f - wy) + bot * wy;
}

// ============================================================================
// launch
// ============================================================================
extern "C" void kernel_launch(void* const* d_in, const int* in_sizes, int n_in,
                              void* d_out, int out_size)
{
    const float* t1_feature = (const float*)d_in[0];
    const float* t2_feature = (const float*)d_in[1];
    const float* t2_pred    = (const float*)d_in[2];
    const float* w_down1    = (const float*)d_in[3];
    const float* w_down2    = (const float*)d_in[4];
    const float* w_flow1    = (const float*)d_in[5];
    const float* bn_gamma   = (const float*)d_in[6];
    const float* bn_beta    = (const float*)d_in[7];
    const float* bn_mean    = (const float*)d_in[8];
    const float* bn_var     = (const float*)d_in[9];
    const float* w_flow2    = (const float*)d_in[10];
    float* out = (float*)d_out;

    k_conv1x1<<<dim3(256, NB, 2), 256>>>(t1_feature, t2_feature, w_down1, w_down2);
    k_conv3x3_bn<<<dim3(Ww / 16, Hh / 16, NB), 256>>>(w_flow1, bn_gamma, bn_beta,
                                                      bn_mean, bn_var);
    k_flowconv<<<dim3(Ww / 32, Hh / 8, NB), 256>>>(w_flow2);
    k_warp<<<(NB * CCLS * HW) / 256, 256>>>(t2_pred, out);
}

// round 2
// speedup vs baseline: 1.0742x; 1.0742x over previous
#include <cuda_runtime.h>
#include <cstdint>

#define Hh 128
#define Ww 256
#define HW (Hh*Ww)
#define NB 4
#define CIN 256
#define Tc 64
#define CCLS 19

typedef unsigned long long u64;

// ---------------- packed f32x2 helpers (sm_100+) ----------------
__device__ __forceinline__ void fma2(u64& d, u64 a, u64 b) {
    asm("fma.rn.f32x2 %0, %1, %2, %0;" : "+l"(d) : "l"(a), "l"(b));
}
__device__ __forceinline__ u64 pack2(float x, float y) {
    u64 r; asm("mov.b64 %0, {%1, %2};" : "=l"(r) : "f"(x), "f"(y)); return r;
}
__device__ __forceinline__ float2 unpack2(u64 v) {
    float2 r; asm("mov.b64 {%0, %1}, %2;" : "=f"(r.x), "=f"(r.y) : "l"(v)); return r;
}

// ---------------- scratch (allocation-free: __device__ globals) ----------------
__device__ float g_y[NB * 128 * HW];    // concat(t1,t2): (4,128,128,256)  ~67MB
__device__ float g_x[NB * Tc * HW];     // after BN+ReLU: (4,64,128,256)   ~33MB
__device__ float g_flow[NB * 2 * HW];   // flow: (4,2,128,256)             ~1MB

// ============================================================================
// Kernel 1: both 1x1 convs (GEMM  C[64,32768] = W[64,256] * X[256,32768])
// block: 64 out-ch x 128 px, 256 threads, microtile 8ch x 4px, packed f32x2
// acc packed along channel pairs: acc2[4 ch-pairs][4 px]
// ============================================================================
__global__ void __launch_bounds__(256) k_conv1x1(
    const float* __restrict__ x1, const float* __restrict__ x2,
    const float* __restrict__ w1, const float* __restrict__ w2)
{
    __shared__ __align__(16) float Ws[32][64];    // [k][t]
    __shared__ __align__(16) float Xs[32][128];   // [k][p]

    const int pt = blockIdx.x;          // 0..255 pixel tile
    const int n  = blockIdx.y;          // batch
    const int wh = blockIdx.z;          // 0: t1 path, 1: t2 path

    const float* X  = (wh ? x2 : x1) + (size_t)n * CIN * HW + pt * 128;
    const float* Wg = wh ? w2 : w1;
    float* Y = g_y + (size_t)(n * 128 + wh * 64) * HW + pt * 128;

    const int tid = threadIdx.x;
    const int cb = (tid >> 5) * 8;      // channel base (warp-uniform)
    const int pb = (tid & 31) * 4;      // pixel base

    u64 acc2[4][4];
#pragma unroll
    for (int i = 0; i < 4; i++)
#pragma unroll
        for (int j = 0; j < 4; j++) acc2[i][j] = 0ull;

    for (int k0 = 0; k0 < 256; k0 += 32) {
        for (int i = tid; i < 2048; i += 256) {
            int t = i & 63, k = i >> 6;
            Ws[k][t] = Wg[t * CIN + k0 + k];
        }
        for (int i = tid; i < 4096; i += 256) {
            int k = i >> 7, p = i & 127;
            Xs[k][p] = X[(size_t)(k0 + k) * HW + p];
        }
        __syncthreads();
#pragma unroll
        for (int k = 0; k < 32; k++) {
            // 8 consecutive weight floats -> 4 packed ch-pairs
            ulonglong2 wa = *(const ulonglong2*)&Ws[k][cb];
            ulonglong2 wb = *(const ulonglong2*)&Ws[k][cb + 4];
            u64 w2v[4] = {wa.x, wa.y, wb.x, wb.y};
            float4 xv = *(const float4*)&Xs[k][pb];
            u64 xd[4] = {pack2(xv.x, xv.x), pack2(xv.y, xv.y),
                         pack2(xv.z, xv.z), pack2(xv.w, xv.w)};
#pragma unroll
            for (int i = 0; i < 4; i++)
#pragma unroll
                for (int j = 0; j < 4; j++) fma2(acc2[i][j], w2v[i], xd[j]);
        }
        __syncthreads();
    }
#pragma unroll
    for (int i = 0; i < 4; i++) {
        float2 v0 = unpack2(acc2[i][0]);
        float2 v1 = unpack2(acc2[i][1]);
        float2 v2 = unpack2(acc2[i][2]);
        float2 v3 = unpack2(acc2[i][3]);
        *(float4*)&Y[(size_t)(cb + 2 * i) * HW + pb]     = make_float4(v0.x, v1.x, v2.x, v3.x);
        *(float4*)&Y[(size_t)(cb + 2 * i + 1) * HW + pb] = make_float4(v0.y, v1.y, v2.y, v3.y);
    }
}

// ============================================================================
// Kernel 2: conv3x3 (128 -> 64, pad 1) + BN + ReLU, packed f32x2
// block tile: 64 out-ch x (16x16 px), 256 threads, microtile 8ch x 8px
// acc packed along channel pairs: acc2[4 ch-pairs][8 px]
// ============================================================================
__global__ void __launch_bounds__(256, 2) k_conv3x3_bn(
    const float* __restrict__ wf,
    const float* __restrict__ gamma, const float* __restrict__ beta,
    const float* __restrict__ mean,  const float* __restrict__ var)
{
    __shared__ __align__(16) float Xs[8 * 18 * 20];   // [cc][row(18)][col pad 20]
    __shared__ __align__(16) float Ws[8 * 9 * 64];    // [cc][tap][t]

    const int bx = blockIdx.x;          // 0..15 (W/16)
    const int by = blockIdx.y;          // 0..7  (H/16)
    const int n  = blockIdx.z;

    const int tid = threadIdx.x;
    const int cb  = (tid >> 5) * 8;     // channel octet (warp-uniform)
    const int g   = tid & 31;
    const int r   = g >> 1;             // 0..15 output row in tile
    const int hx  = (g & 1) * 8;        // 0 or 8: output col base

    u64 acc2[4][8];
#pragma unroll
    for (int i = 0; i < 4; i++)
#pragma unroll
        for (int j = 0; j < 8; j++) acc2[i][j] = 0ull;

    const float* Yb = g_y + (size_t)n * 128 * HW;

    for (int ch0 = 0; ch0 < 128; ch0 += 8) {
        // stage input halo tile 8 x 18 x 18
        for (int i = tid; i < 8 * 18 * 18; i += 256) {
            int cc = i / 324;
            int rem = i - cc * 324;
            int ry = rem / 18, rx = rem - (rem / 18) * 18;
            int gy = by * 16 + ry - 1;
            int gx = bx * 16 + rx - 1;
            float v = 0.f;
            if ((unsigned)gy < (unsigned)Hh && (unsigned)gx < (unsigned)Ww)
                v = Yb[(size_t)(ch0 + cc) * HW + gy * Ww + gx];
            Xs[cc * 360 + ry * 20 + rx] = v;
        }
        // stage weights as [cc][tap][t]
        for (int i = tid; i < 8 * 9 * 64; i += 256) {
            int t = i & 63;
            int tap = (i >> 6) % 9;
            int cc = i / 576;
            Ws[cc * 576 + tap * 64 + t] = wf[t * (128 * 9) + (ch0 + cc) * 9 + tap];
        }
        __syncthreads();

#pragma unroll
        for (int cc = 0; cc < 8; cc++) {
#pragma unroll
            for (int dy = 0; dy < 3; dy++) {
                const float* xp = &Xs[cc * 360 + (r + dy) * 20 + hx];
                float4 xa = *(const float4*)&xp[0];
                float4 xb = *(const float4*)&xp[4];
                float4 xc = *(const float4*)&xp[8];
                // hoisted pixel dups, shared across the 3 dx taps
                u64 xd[10];
                xd[0] = pack2(xa.x, xa.x); xd[1] = pack2(xa.y, xa.y);
                xd[2] = pack2(xa.z, xa.z); xd[3] = pack2(xa.w, xa.w);
                xd[4] = pack2(xb.x, xb.x); xd[5] = pack2(xb.y, xb.y);
                xd[6] = pack2(xb.z, xb.z); xd[7] = pack2(xb.w, xb.w);
                xd[8] = pack2(xc.x, xc.x); xd[9] = pack2(xc.y, xc.y);
#pragma unroll
                for (int dx = 0; dx < 3; dx++) {
                    const float* wp = &Ws[cc * 576 + (dy * 3 + dx) * 64 + cb];
                    ulonglong2 wa = *(const ulonglong2*)&wp[0];
                    ulonglong2 wb = *(const ulonglong2*)&wp[4];
                    u64 w2v[4] = {wa.x, wa.y, wb.x, wb.y};
#pragma unroll
                    for (int i = 0; i < 4; i++)
#pragma unroll
                        for (int j = 0; j < 8; j++)
                            fma2(acc2[i][j], w2v[i], xd[dx + j]);
                }
            }
        }
        __syncthreads();
    }

    // epilogue: BN + ReLU, store to g_x (unpack channel pairs)
    const int oy = by * 16 + r;
    const int ox = bx * 16 + hx;
#pragma unroll
    for (int i = 0; i < 4; i++) {
        int t0 = cb + 2 * i, t1 = t0 + 1;
        float s0 = gamma[t0] * rsqrtf(var[t0] + 1e-5f);
        float b0 = beta[t0] - mean[t0] * s0;
        float s1 = gamma[t1] * rsqrtf(var[t1] + 1e-5f);
        float b1 = beta[t1] - mean[t1] * s1;
        float o0[8], o1[8];
#pragma unroll
        for (int j = 0; j < 8; j++) {
            float2 v = unpack2(acc2[i][j]);
            float a0 = v.x * s0 + b0;
            float a1 = v.y * s1 + b1;
            o0[j] = a0 > 0.f ? a0 : 0.f;
            o1[j] = a1 > 0.f ? a1 : 0.f;
        }
        float* d0 = g_x + (size_t)((n * Tc + t0) * Hh + oy) * Ww + ox;
        float* d1 = g_x + (size_t)((n * Tc + t1) * Hh + oy) * Ww + ox;
        *(float4*)&d0[0] = make_float4(o0[0], o0[1], o0[2], o0[3]);
        *(float4*)&d0[4] = make_float4(o0[4], o0[5], o0[6], o0[7]);
        *(float4*)&d1[0] = make_float4(o1[0], o1[1], o1[2], o1[3]);
        *(float4*)&d1[4] = make_float4(o1[4], o1[5], o1[6], o1[7]);
    }
}

// ============================================================================
// Kernel 3: conv3x3 (64 -> 2, pad 1) -> flow
// ============================================================================
__global__ void __launch_bounds__(256) k_flowconv(const float* __restrict__ w2)
{
    __shared__ __align__(16) float Xs[8 * 10 * 36];   // [cc][row(10)][col(34) pad 36]
    __shared__ __align__(16) float Ws[2 * 64 * 9];

    const int bx = blockIdx.x;          // 0..7  (W/32)
    const int by = blockIdx.y;          // 0..15 (H/8)
    const int n  = blockIdx.z;

    const int tid = threadIdx.x;
    const int py = tid >> 5;            // 0..7
    const int px = tid & 31;            // 0..31

    for (int i = tid; i < 1152; i += 256) Ws[i] = w2[i];

    float a0 = 0.f, a1 = 0.f;
    const float* Xb = g_x + (size_t)n * Tc * HW;

    for (int c0 = 0; c0 < 64; c0 += 8) {
        for (int i = tid; i < 8 * 10 * 34; i += 256) {
            int cc = i / 340;
            int rem = i - cc * 340;
            int ry = rem / 34, rx = rem - (rem / 34) * 34;
            int gy = by * 8 + ry - 1;
            int gx = bx * 32 + rx - 1;
            float v = 0.f;
            if ((unsigned)gy < (unsigned)Hh && (unsigned)gx < (unsigned)Ww)
                v = Xb[(size_t)(c0 + cc) * HW + gy * Ww + gx];
            Xs[cc * 360 + ry * 36 + rx] = v;
        }
        __syncthreads();
#pragma unroll
        for (int cc = 0; cc < 8; cc++) {
            int c = c0 + cc;
#pragma unroll
            for (int dy = 0; dy < 3; dy++) {
#pragma unroll
                for (int dx = 0; dx < 3; dx++) {
                    float xv = Xs[cc * 360 + (py + dy) * 36 + (px + dx)];
                    int tap = dy * 3 + dx;
                    a0 += Ws[c * 9 + tap] * xv;
                    a1 += Ws[(64 + c) * 9 + tap] * xv;
                }
            }
        }
        __syncthreads();
    }

    const int oy = by * 8 + py, ox = bx * 32 + px;
    g_flow[((size_t)(n * 2 + 0) * Hh + oy) * Ww + ox] = a0;
    g_flow[((size_t)(n * 2 + 1) * Hh + oy) * Ww + ox] = a1;
}

// ============================================================================
// Kernel 4: flow_warp with torch repeat(c,1,1,1) batch-aliasing
// ============================================================================
__global__ void __launch_bounds__(256) k_warp(
    const float* __restrict__ pred, float* __restrict__ out)
{
    const int idx = blockIdx.x * 256 + threadIdx.x;
    const int x = idx & (Ww - 1);
    const int y = (idx >> 8) & (Hh - 1);
    const int t = idx >> 15;                          // n*19+ch, 0..75
    const int fb = t & 3;                             // (n*19+ch)%4

    const float fx = g_flow[((size_t)(fb * 2 + 0) * Hh + y) * Ww + x];
    const float fy = g_flow[((size_t)(fb * 2 + 1) * Hh + y) * Ww + x];

    const float gx = -1.f + 2.f * (float)x / (float)(Ww - 1);
    const float gy = -1.f + 2.f * (float)y / (float)(Hh - 1);
    const float sx = gx + fx / (float)Ww;
    const float sy = gy + fy / (float)Hh;
    const float ix = ((sx + 1.f) * (float)Ww - 1.f) * 0.5f;
    const float iy = ((sy + 1.f) * (float)Hh - 1.f) * 0.5f;

    const float x0f = floorf(ix), y0f = floorf(iy);
    const float wx = ix - x0f, wy = iy - y0f;
    const int x0 = (int)x0f, y0 = (int)y0f;

    const float* img = pred + (size_t)t * HW;
    auto samp = [&](int yy, int xx) -> float {
        return (xx >= 0 && xx < Ww && yy >= 0 && yy < Hh) ? img[yy * Ww + xx] : 0.f;
    };
    const float v00 = samp(y0, x0);
    const float v01 = samp(y0, x0 + 1);
    const float v10 = samp(y0 + 1, x0);
    const float v11 = samp(y0 + 1, x0 + 1);

    const float top = v00 * (1.f - wx) + v01 * wx;
    const float bot = v10 * (1.f - wx) + v11 * wx;
    out[idx] = top * (1.f - wy) + bot * wy;
}

// ============================================================================
// launch
// ============================================================================
extern "C" void kernel_launch(void* const* d_in, const int* in_sizes, int n_in,
                              void* d_out, int out_size)
{
    const float* t1_feature = (const float*)d_in[0];
    const float* t2_feature = (const float*)d_in[1];
    const float* t2_pred    = (const float*)d_in[2];
    const float* w_down1    = (const float*)d_in[3];
    const float* w_down2    = (const float*)d_in[4];
    const float* w_flow1    = (const float*)d_in[5];
    const float* bn_gamma   = (const float*)d_in[6];
    const float* bn_beta    = (const float*)d_in[7];
    const float* bn_mean    = (const float*)d_in[8];
    const float* bn_var     = (const float*)d_in[9];
    const float* w_flow2    = (const float*)d_in[10];
    float* out = (float*)d_out;

    k_conv1x1<<<dim3(256, NB, 2), 256>>>(t1_feature, t2_feature, w_down1, w_down2);
    k_conv3x3_bn<<<dim3(Ww / 16, Hh / 16, NB), 256>>>(w_flow1, bn_gamma, bn_beta,
                                                      bn_mean, bn_var);
    k_flowconv<<<dim3(Ww / 32, Hh / 8, NB), 256>>>(w_flow2);
    k_warp<<<(NB * CCLS * HW) / 256, 256>>>(t2_pred, out);
}